// round 4
// baseline (speedup 1.0000x reference)
#include <cuda_runtime.h>
#include <math.h>

#define NN    2048
#define BG    8
#define NODES (NN*BG)
#define KNNK  4
#define INC   16
#define HIDD  128
#define NC    64
#define EMAX  262144

// ---------------- scratch (no allocs allowed) ----------------
__device__ float g_y  [NODES*HIDD];   // xw1 (unscaled)
__device__ float g_h1 [NODES*HIDD];
__device__ float g_xw2[NODES*HIDD];
__device__ float g_h2 [NODES*HIDD];
__device__ float g_s  [NODES*NC];     // aligned copy of s for float4 reads
__device__ float g_coord[3*NODES];
__device__ float g_pool[BG*NC*HIDD];
__device__ float g_ss [BG*NC*NC];
__device__ float g_ca [BG*NC];
__device__ float g_ssum[BG*NC];
__device__ float g_tr [BG];           // 0 at entry (restored at tail)
__device__ int   g_cnt [NODES];       // 0 at entry (restored at tail)
__device__ int   g_rowptr[NODES];
__device__ int   g_pos [NODES];
__device__ int   g_eidx[EMAX];
__device__ int   g_ecnt[BG];          // 0 at entry (restored at tail)
__device__ int   g_knn [NODES*KNNK];

// ================= K1: xw1 (16 nodes/block, W1 in smem)  ||  degree histogram =================
#define XW1_BLKS 1024
#define HIST_BLKS 512
__global__ void k_front(const float* __restrict__ x, const float* __restrict__ W1,
                        const int* __restrict__ src, const int* __restrict__ dst, int E) {
    int t = threadIdx.x;
    if (blockIdx.x < XW1_BLKS) {
        __shared__ float w1s[INC*HIDD];
        __shared__ float xs[16*INC];
        for (int i = t; i < INC*HIDD; i += 128) w1s[i] = W1[i];
        int n0 = blockIdx.x*16;
        for (int i = t; i < 16*INC; i += 128) xs[i] = x[n0*INC + i];
        __syncthreads();
#pragma unroll
        for (int r = 0; r < 16; r++) {
            float a = 0.f;
#pragma unroll
            for (int k = 0; k < INC; k++) a += xs[r*INC + k] * w1s[k*HIDD + t];
            g_y[(n0 + r)*HIDD + t] = a;
        }
    } else {
        int i0 = (blockIdx.x - XW1_BLKS)*128 + t;
        for (int e = i0; e < E; e += HIST_BLKS*128) {
            atomicAdd(&g_cnt[dst[e]], 1);
            atomicAdd(&g_ecnt[src[e]/NN], 1);
        }
    }
}

// ================= K2: exclusive scan of g_cnt =================
__global__ void k_scan() {
    __shared__ int wsum[32];
    int t = threadIdx.x, lane = t & 31, w = t >> 5;
    int base = t*16;
    int loc[16]; int s = 0;
#pragma unroll
    for (int i = 0; i < 16; i++) { loc[i] = s; s += g_cnt[base + i]; }
    int v = s;
#pragma unroll
    for (int o = 1; o < 32; o <<= 1) { int u = __shfl_up_sync(~0u, v, o); if (lane >= o) v += u; }
    if (lane == 31) wsum[w] = v;
    __syncthreads();
    if (w == 0) {
        int u = wsum[lane];
#pragma unroll
        for (int o = 1; o < 32; o <<= 1) { int xx = __shfl_up_sync(~0u, u, o); if (lane >= o) u += xx; }
        wsum[lane] = u;
    }
    __syncthreads();
    int excl = v - s + (w ? wsum[w-1] : 0);
#pragma unroll
    for (int i = 0; i < 16; i++) { int off = excl + loc[i]; g_rowptr[base+i] = off; g_pos[base+i] = off; }
}

// ================= K3: bucket edges by dst =================
__global__ void k_fill(const int* __restrict__ src, const int* __restrict__ dst, int E) {
    int e = blockIdx.x*blockDim.x + threadIdx.x;
    if (e < E) {
        int p = atomicAdd(&g_pos[dst[e]], 1);
        g_eidx[p] = src[e];
    }
}

// ================= K4: GCN1 gather (per-src scaled) + relu + coords =================
__global__ void k_gcn1(const float* __restrict__ b1) {
    __shared__ int   idxs[512];
    __shared__ float wts [512];
    int n = blockIdx.x, c = threadIdx.x;
    int beg = g_rowptr[n], cnt = g_cnt[n];
    int lim = cnt < 512 ? cnt : 512;
    for (int i = c; i < lim; i += HIDD) {
        int idx = g_eidx[beg + i];
        idxs[i] = idx;
        wts[i]  = rsqrtf((float)(g_cnt[idx] + 1));
    }
    __syncthreads();
    float rsn = rsqrtf((float)(cnt + 1));
    float acc = g_y[n*HIDD + c] * rsn;
#pragma unroll 4
    for (int i = 0; i < lim; i++) acc += g_y[idxs[i]*HIDD + c] * wts[i];
    for (int i = 512; i < cnt; i++) {
        int idx = g_eidx[beg + i];
        acc += g_y[idx*HIDD + c] * rsqrtf((float)(g_cnt[idx] + 1));
    }
    float v = fmaxf(acc * rsn + b1[c], 0.f);
    g_h1[n*HIDD + c] = v;
    if (c < 3) g_coord[c*NODES + n] = v;
}

// ================= K5: kNN (128 blocks)  ||  xw2 = h1@W2 (512 blocks, 32 rows) =================
#define KNN_BLKS 128
#define XW2_BLKS 512
__global__ void k_mid(const float* __restrict__ W2) {
    __shared__ __align__(16) float sh[6144];   // 24KB: knn coords / xw2 A-tile
    int t = threadIdx.x;
    if (blockIdx.x < KNN_BLKS) {
        float* cx = sh; float* cy = sh + NN; float* cz = sh + 2*NN;
        int b = blockIdx.x >> 4, base = b*NN;
        for (int j = t; j < NN; j += 128) {
            cx[j] = g_coord[base + j];
            cy[j] = g_coord[NODES + base + j];
            cz[j] = g_coord[2*NODES + base + j];
        }
        __syncthreads();
        int i = (blockIdx.x & 15)*128 + t;
        float xi = cx[i], yi = cy[i], zi = cz[i];
        float bd[KNNK]; int bi[KNNK];
#pragma unroll
        for (int q = 0; q < KNNK; q++) { bd[q] = 1e30f; bi[q] = NN; }
        for (int j = 0; j < NN; j++) {
            if (j == i) continue;
            float dx = xi - cx[j], dy = yi - cy[j], dz = zi - cz[j];
            float d2 = dx*dx + dy*dy + dz*dz;
            if (d2 < bd[3]) {
                bd[3] = d2; bi[3] = j;
#pragma unroll
                for (int q = 3; q > 0; q--) {
                    if (bd[q] < bd[q-1]) {
                        float td = bd[q]; bd[q] = bd[q-1]; bd[q-1] = td;
                        int ti = bi[q]; bi[q] = bi[q-1]; bi[q-1] = ti;
                    }
                }
            }
        }
#pragma unroll
        for (int q = 0; q < KNNK; q++) g_knn[(base + i)*KNNK + q] = base + bi[q];
    } else {
        int r0 = (blockIdx.x - KNN_BLKS)*32;
        for (int r = 0; r < 32; r++) sh[r*HIDD + t] = g_h1[(r0 + r)*HIDD + t];
        __syncthreads();
        float acc[32];
#pragma unroll
        for (int r = 0; r < 32; r++) acc[r] = 0.f;
        for (int k = 0; k < HIDD; k += 4) {
            float b0 = W2[(k+0)*HIDD + t], b1v = W2[(k+1)*HIDD + t];
            float b2v = W2[(k+2)*HIDD + t], b3 = W2[(k+3)*HIDD + t];
#pragma unroll
            for (int r = 0; r < 32; r++) {
                float4 a = *(const float4*)&sh[r*HIDD + k];
                acc[r] += a.x*b0 + a.y*b1v + a.z*b2v + a.w*b3;
            }
        }
        for (int r = 0; r < 32; r++) g_xw2[(r0 + r)*HIDD + t] = acc[r];
    }
}

// ================= K6: GCN2 (deg=5) + relu + softmax(s) fused; writes h2, g_s, sout =================
__global__ void k_gcn2s(const float* __restrict__ b2, const float* __restrict__ Wp,
                        const float* __restrict__ bp, float* __restrict__ sout) {
    __shared__ float hr[HIDD];
    __shared__ float part[2][NC];
    __shared__ float red[NC];
    int n = blockIdx.x, t = threadIdx.x;
    const float nf = 0.19999999999999998f;
    int k0 = g_knn[n*KNNK+0], k1 = g_knn[n*KNNK+1], k2 = g_knn[n*KNNK+2], k3 = g_knn[n*KNNK+3];
    float v = (g_xw2[n*HIDD+t] + g_xw2[k0*HIDD+t] + g_xw2[k1*HIDD+t]
             + g_xw2[k2*HIDD+t] + g_xw2[k3*HIDD+t]) * nf + b2[t];
    v = fmaxf(v, 0.f);
    g_h2[n*HIDD + t] = v;
    hr[t] = v;
    __syncthreads();
    int c = t & 63, half = t >> 6;
    float a = 0.f;
#pragma unroll 8
    for (int k = half*64; k < half*64 + 64; k++) a += hr[k] * Wp[k*NC + c];
    part[half][c] = a;
    __syncthreads();
    float logit = part[0][c] + part[1][c] + bp[c];
    if (half == 0) red[c] = logit;
    __syncthreads();
    for (int o = 32; o; o >>= 1) { if (t < o) red[t] = fmaxf(red[t], red[t+o]); __syncthreads(); }
    float mx = red[0]; __syncthreads();
    float e = expf(logit - mx);
    if (half == 0) red[c] = e;
    __syncthreads();
    for (int o = 32; o; o >>= 1) { if (t < o) red[t] += red[t+o]; __syncthreads(); }
    if (half == 0) {
        float sv = e / red[0];
        g_s[n*NC + c]  = sv;
        sout[n*NC + c] = sv;
    }
}

// ================= K7: pool || ss || ca || trace, one kernel =================
#define POOL_BLKS 64
#define SSK_BLKS  64
#define CA_BLKS   8
#define TR_BLKS   256
__global__ void k_stats(const int* __restrict__ src, const int* __restrict__ dst, int E) {
    int t = threadIdx.x;
    if (blockIdx.x < POOL_BLKS) {
        __shared__ __align__(16) float4 ssm[128][2];
        int b = blockIdx.x >> 3, cg = blockIdx.x & 7;
        int base = b*NN;
        float acc[8];
#pragma unroll
        for (int j = 0; j < 8; j++) acc[j] = 0.f;
        for (int nt = 0; nt < NN; nt += 128) {
            const float4* sp = (const float4*)&g_s[(base + nt + t)*NC + cg*8];
            ssm[t][0] = sp[0]; ssm[t][1] = sp[1];
            __syncthreads();
#pragma unroll 4
            for (int nn = 0; nn < 128; nn++) {
                float xv = g_h2[(base + nt + nn)*HIDD + t];
                float4 s0 = ssm[nn][0], s1 = ssm[nn][1];
                acc[0] += s0.x*xv; acc[1] += s0.y*xv; acc[2] += s0.z*xv; acc[3] += s0.w*xv;
                acc[4] += s1.x*xv; acc[5] += s1.y*xv; acc[6] += s1.z*xv; acc[7] += s1.w*xv;
            }
            __syncthreads();
        }
#pragma unroll
        for (int j = 0; j < 8; j++) g_pool[(b*NC + cg*8 + j)*HIDD + t] = acc[j];
    } else if (blockIdx.x < POOL_BLKS + SSK_BLKS) {
        __shared__ __align__(16) float4 ssm2[128][2];
        __shared__ float comb[8][64];
        int idx = blockIdx.x - POOL_BLKS;
        int b = idx >> 3, cg = idx & 7;
        int base = b*NN;
        int d = t & 63, half = t >> 6;
        float acc[8];
#pragma unroll
        for (int j = 0; j < 8; j++) acc[j] = 0.f;
        for (int nt = 0; nt < NN; nt += 128) {
            const float4* sp = (const float4*)&g_s[(base + nt + t)*NC + cg*8];
            ssm2[t][0] = sp[0]; ssm2[t][1] = sp[1];
            __syncthreads();
#pragma unroll 4
            for (int nn = half*64; nn < half*64 + 64; nn++) {
                float xv = g_s[(base + nt + nn)*NC + d];
                float4 s0 = ssm2[nn][0], s1 = ssm2[nn][1];
                acc[0] += s0.x*xv; acc[1] += s0.y*xv; acc[2] += s0.z*xv; acc[3] += s0.w*xv;
                acc[4] += s1.x*xv; acc[5] += s1.y*xv; acc[6] += s1.z*xv; acc[7] += s1.w*xv;
            }
            __syncthreads();
        }
        if (half == 1) {
#pragma unroll
            for (int j = 0; j < 8; j++) comb[j][d] = acc[j];
        }
        __syncthreads();
        if (half == 0) {
#pragma unroll
            for (int j = 0; j < 8; j++)
                g_ss[b*NC*NC + (cg*8 + j)*NC + d] = acc[j] + comb[j][d];
        }
    } else if (blockIdx.x < POOL_BLKS + SSK_BLKS + CA_BLKS) {
        __shared__ float cc[2][64], cs[2][64];
        int b = blockIdx.x - (POOL_BLKS + SSK_BLKS);
        int c = t & 63, half = t >> 6;
        float ca = 0.f, su = 0.f;
        int n0 = half*1024;
#pragma unroll 4
        for (int n = n0; n < n0 + 1024; n++) {
            float sv = g_s[(b*NN + n)*NC + c];
            ca += sv * (float)g_cnt[b*NN + n];
            su += sv;
        }
        cc[half][c] = ca; cs[half][c] = su;
        __syncthreads();
        if (half == 0) {
            g_ca[b*NC + c]   = ca + cc[1][c];
            g_ssum[b*NC + c] = su + cs[1][c];
        }
    } else {
        __shared__ float bins[BG];
        if (t < BG) bins[t] = 0.f;
        __syncthreads();
        int lane8 = t & 7;
        int slot = (blockIdx.x - (POOL_BLKS + SSK_BLKS + CA_BLKS))*16 + (t >> 3);
        for (int e = slot; e < E; e += TR_BLKS*16) {
            int a = src[e], d = dst[e];
            const float4* sa = (const float4*)&g_s[a*NC];
            const float4* sd = (const float4*)&g_s[d*NC];
            float4 a0 = sa[lane8*2], a1 = sa[lane8*2 + 1];
            float4 d0 = sd[lane8*2], d1 = sd[lane8*2 + 1];
            float v = a0.x*d0.x + a0.y*d0.y + a0.z*d0.z + a0.w*d0.w
                    + a1.x*d1.x + a1.y*d1.y + a1.z*d1.z + a1.w*d1.w;
            v += __shfl_xor_sync(0xffffffffu, v, 4, 8);
            v += __shfl_xor_sync(0xffffffffu, v, 2, 8);
            v += __shfl_xor_sync(0xffffffffu, v, 1, 8);
            if (lane8 == 0) atomicAdd(&bins[a >> 11], v);
        }
        __syncthreads();
        if (t < BG) atomicAdd(&g_tr[t], bins[t]);
    }
}

// ================= K8: selu+log_softmax || loss || state re-zero =================
__global__ void k_tail(float* __restrict__ out, float* __restrict__ loss_out) {
    int t = threadIdx.x;
    if (blockIdx.x < 512) {
        __shared__ float red[HIDD];
        int row = blockIdx.x;
        float v = g_pool[row*HIDD + t];
        const float alpha = 1.6732632423543772f, scale = 1.0507009873554805f;
        v = scale * (v > 0.f ? v : alpha * expm1f(v));
        red[t] = v; __syncthreads();
        for (int o = 64; o; o >>= 1) { if (t < o) red[t] = fmaxf(red[t], red[t+o]); __syncthreads(); }
        float mx = red[0]; __syncthreads();
        float e = expf(v - mx);
        red[t] = e; __syncthreads();
        for (int o = 64; o; o >>= 1) { if (t < o) red[t] += red[t+o]; __syncthreads(); }
        out[row*HIDD + t] = v - mx - logf(red[0]);
    } else if (blockIdx.x == 512) {
        __shared__ float red[128];
        float spectral = 0.f, ortho = 0.f, cluster = 0.f;
        for (int b = 0; b < BG; b++) {
            float p = 0.f;
            for (int i = t; i < NC*NC; i += 128) { float v = g_ss[b*NC*NC + i]; p += v*v; }
            red[t] = p; __syncthreads();
            for (int o = 64; o; o >>= 1) { if (t < o) red[t] += red[t+o]; __syncthreads(); }
            float fro = sqrtf(red[0]); __syncthreads();
            p = 0.f;
            for (int i = t; i < NC*NC; i += 128) {
                float v = g_ss[b*NC*NC + i] / fro;
                if ((i >> 6) == (i & 63)) v -= 0.125f;
                p += v*v;
            }
            red[t] = p; __syncthreads();
            for (int o = 64; o; o >>= 1) { if (t < o) red[t] += red[t+o]; __syncthreads(); }
            ortho += sqrtf(red[0]); __syncthreads();
            p = 0.f;
            if (t < NC) { float v = g_ca[b*NC + t]; p = v*v; }
            red[t] = p; __syncthreads();
            for (int o = 64; o; o >>= 1) { if (t < o) red[t] += red[t+o]; __syncthreads(); }
            float ca2 = red[0]; __syncthreads();
            float m = 0.5f * (float)g_ecnt[b];
            spectral += -(g_tr[b] - ca2 / (2.f*m)) / (2.f*m);
            p = 0.f;
            if (t < NC) { float v = g_ssum[b*NC + t]; p = v*v; }
            red[t] = p; __syncthreads();
            for (int o = 64; o; o >>= 1) { if (t < o) red[t] += red[t+o]; __syncthreads(); }
            cluster += sqrtf(red[0]) / (float)NN * 8.f - 1.f; __syncthreads();
        }
        if (t == 0)
            loss_out[0] = spectral / (float)BG + ortho / (float)BG + cluster / (float)BG;
        __syncthreads();
        if (t < BG) { g_tr[t] = 0.f; g_ecnt[t] = 0; }   // restore invariants
    } else {
        int i0 = (blockIdx.x - 513)*128 + t;
        for (int k = i0; k < NODES; k += 32*128) g_cnt[k] = 0;
    }
}

// ---------------- launch ----------------
extern "C" void kernel_launch(void* const* d_in, const int* in_sizes, int n_in,
                              void* d_out, int out_size) {
    const float* x    = (const float*)d_in[0];
    const int*   esrc = (const int*)  d_in[1];
    const int*   edst = (const int*)  d_in[2];
    const float* W1   = (const float*)d_in[4];
    const float* b1   = (const float*)d_in[5];
    const float* W2   = (const float*)d_in[6];
    const float* b2   = (const float*)d_in[7];
    const float* Wp   = (const float*)d_in[8];
    const float* bp   = (const float*)d_in[9];
    float* out = (float*)d_out;
    int E = in_sizes[1];

    float* loss_out = out + BG*NC*HIDD;        // [65536]
    float* sout     = out + BG*NC*HIDD + 1;    // [65537 ..)

    k_front<<<XW1_BLKS + HIST_BLKS, 128>>>(x, W1, esrc, edst, E);
    k_scan <<<1, 1024>>>();
    k_fill <<<(E + 255)/256, 256>>>(esrc, edst, E);
    k_gcn1 <<<NODES, HIDD>>>(b1);
    k_mid  <<<KNN_BLKS + XW2_BLKS, 128>>>(W2);
    k_gcn2s<<<NODES, HIDD>>>(b2, Wp, bp, sout);
    k_stats<<<POOL_BLKS + SSK_BLKS + CA_BLKS + TR_BLKS, 128>>>(esrc, edst, E);
    k_tail <<<512 + 1 + 32, 128>>>(out, loss_out);
}

// round 5
// speedup vs baseline: 1.1878x; 1.1878x over previous
#include <cuda_runtime.h>
#include <math.h>

#define NN    2048
#define BG    8
#define NODES (NN*BG)
#define KNNK  4
#define INC   16
#define HIDD  128
#define NC    64
#define EMAX  262144

// ---------------- scratch (no allocs allowed) ----------------
__device__ float g_y  [NODES*HIDD];   // xw1 * rsqrt(deg)
__device__ float g_h1 [NODES*HIDD];
__device__ float g_xw2[NODES*HIDD];
__device__ float g_h2 [NODES*HIDD];
__device__ float g_coord[3*NODES];    // h1[:, 0:3] compact (SoA)
__device__ float g_pool[BG*NC*HIDD];
__device__ float g_ss [BG*NC*NC];
__device__ float g_ca [BG*NC];
__device__ float g_ssum[BG*NC];
__device__ float g_tr [BG];
__device__ int   g_cnt [NODES];
__device__ int   g_rowptr[NODES];
__device__ int   g_pos [NODES];
__device__ int   g_eidx[EMAX];
__device__ int   g_ecnt[BG];
__device__ int   g_knn [NODES*KNNK];

// ---------------- kernels ----------------
__global__ void k_zero() {
    int i = blockIdx.x*blockDim.x + threadIdx.x;
    if (i < NODES) g_cnt[i] = 0;
    if (i < BG*NC*HIDD) g_pool[i] = 0.f;
    if (i < BG*NC*NC) g_ss[i] = 0.f;
    if (i < BG*NC) { g_ca[i] = 0.f; g_ssum[i] = 0.f; }
    if (i < BG) { g_ecnt[i] = 0; g_tr[i] = 0.f; }
}

// in-degree histogram (original edges) + per-graph edge counts
__global__ void k_hist(const int* __restrict__ src, const int* __restrict__ dst, int E) {
    int e = blockIdx.x*blockDim.x + threadIdx.x;
    if (e < E) {
        atomicAdd(&g_cnt[dst[e]], 1);
        atomicAdd(&g_ecnt[src[e]/NN], 1);
    }
}

// exclusive prefix sum of g_cnt -> g_rowptr, g_pos (one block, 1024 thr, 16 each)
__global__ void k_scan() {
    __shared__ int wsum[32];
    int t = threadIdx.x, lane = t & 31, w = t >> 5;
    int base = t*16;
    int loc[16]; int s = 0;
#pragma unroll
    for (int i = 0; i < 16; i++) { loc[i] = s; s += g_cnt[base + i]; }
    int v = s;
#pragma unroll
    for (int o = 1; o < 32; o <<= 1) { int u = __shfl_up_sync(~0u, v, o); if (lane >= o) v += u; }
    if (lane == 31) wsum[w] = v;
    __syncthreads();
    if (w == 0) {
        int u = wsum[lane];
#pragma unroll
        for (int o = 1; o < 32; o <<= 1) { int x = __shfl_up_sync(~0u, u, o); if (lane >= o) u += x; }
        wsum[lane] = u;
    }
    __syncthreads();
    int excl = v - s + (w ? wsum[w-1] : 0);
#pragma unroll
    for (int i = 0; i < 16; i++) { int off = excl + loc[i]; g_rowptr[base+i] = off; g_pos[base+i] = off; }
}

// bucket edges by dst
__global__ void k_fill(const int* __restrict__ src, const int* __restrict__ dst, int E) {
    int e = blockIdx.x*blockDim.x + threadIdx.x;
    if (e < E) {
        int p = atomicAdd(&g_pos[dst[e]], 1);
        g_eidx[p] = src[e];
    }
}

// y = (x @ W1) * rsqrt(deg)   ([16384,16]@[16,128])
__global__ void k_xw1y(const float* __restrict__ x, const float* __restrict__ W1) {
    __shared__ float xr[INC];
    int n = blockIdx.x, c = threadIdx.x;
    if (c < INC) xr[c] = x[n*INC + c];
    __syncthreads();
    float a = 0.f;
#pragma unroll
    for (int k = 0; k < INC; k++) a += xr[k] * W1[k*HIDD + c];
    g_y[n*HIDD + c] = a * rsqrtf((float)(g_cnt[n] + 1));
}

// GCN1 gather: h1[n] = relu(rsqrt(deg)*(y[n] + sum y[src]) + b1); also emit coords
__global__ void k_gcn1(const float* __restrict__ b1) {
    __shared__ int idxs[512];
    int n = blockIdx.x, c = threadIdx.x;
    int beg = g_rowptr[n], cnt = g_cnt[n];
    int lim = cnt < 512 ? cnt : 512;
    for (int i = c; i < lim; i += HIDD) idxs[i] = g_eidx[beg + i];
    __syncthreads();
    float acc = g_y[n*HIDD + c];
#pragma unroll 4
    for (int i = 0; i < lim; i++) acc += g_y[idxs[i]*HIDD + c];
    for (int i = 512; i < cnt; i++) acc += g_y[g_eidx[beg + i]*HIDD + c];
    float v = acc * rsqrtf((float)(cnt + 1)) + b1[c];
    v = fmaxf(v, 0.f);
    g_h1[n*HIDD + c] = v;
    if (c < 3) g_coord[c*NODES + n] = v;
}

// kNN (K=4) on coords per graph; grid (BG, NN/128), 128 thr
__global__ void k_knn() {
    __shared__ float cx[NN], cy[NN], cz[NN];
    int b = blockIdx.x, base = b*NN;
    for (int j = threadIdx.x; j < NN; j += blockDim.x) {
        cx[j] = g_coord[0*NODES + base + j];
        cy[j] = g_coord[1*NODES + base + j];
        cz[j] = g_coord[2*NODES + base + j];
    }
    __syncthreads();
    int i = blockIdx.y*blockDim.x + threadIdx.x;
    float xi = cx[i], yi = cy[i], zi = cz[i];
    float bd[KNNK]; int bi[KNNK];
#pragma unroll
    for (int t = 0; t < KNNK; t++) { bd[t] = 1e30f; bi[t] = NN; }
    for (int j = 0; j < NN; j++) {
        if (j == i) continue;
        float dx = xi - cx[j], dy = yi - cy[j], dz = zi - cz[j];
        float d2 = dx*dx + dy*dy + dz*dz;
        if (d2 < bd[3]) {
            bd[3] = d2; bi[3] = j;
#pragma unroll
            for (int t = 3; t > 0; t--) {
                if (bd[t] < bd[t-1]) {
                    float td = bd[t]; bd[t] = bd[t-1]; bd[t-1] = td;
                    int ti = bi[t]; bi[t] = bi[t-1]; bi[t-1] = ti;
                }
            }
        }
    }
#pragma unroll
    for (int t = 0; t < KNNK; t++) g_knn[(base + i)*KNNK + t] = base + bi[t];
}

// xw2 = h1 @ W2   ([16384,128]@[128,128]) — 32 rows per block, float4 A reads
__global__ void k_xw2(const float* __restrict__ W2) {
    __shared__ __align__(16) float As[32*HIDD];
    int r0 = blockIdx.x * 32, c = threadIdx.x;
    for (int r = 0; r < 32; r++) As[r*HIDD + c] = g_h1[(r0 + r)*HIDD + c];
    __syncthreads();
    float acc[32];
#pragma unroll
    for (int r = 0; r < 32; r++) acc[r] = 0.f;
    for (int k = 0; k < HIDD; k += 4) {
        float b0 = W2[(k+0)*HIDD + c], b1 = W2[(k+1)*HIDD + c];
        float b2 = W2[(k+2)*HIDD + c], b3 = W2[(k+3)*HIDD + c];
#pragma unroll
        for (int r = 0; r < 32; r++) {
            float4 a = *(const float4*)&As[r*HIDD + k];
            acc[r] += a.x*b0 + a.y*b1 + a.z*b2 + a.w*b3;
        }
    }
    for (int r = 0; r < 32; r++) g_xw2[(r0 + r)*HIDD + c] = acc[r];
}

// GCN2: deg==5 everywhere -> norm = rsqrt(5)^2 on every term incl. self-loop
__global__ void k_gcn2(const float* __restrict__ b2) {
    int n = blockIdx.x, c = threadIdx.x;
    float nf = rsqrtf(5.0f); nf = nf * nf;
    int k0 = g_knn[n*KNNK+0], k1 = g_knn[n*KNNK+1], k2 = g_knn[n*KNNK+2], k3 = g_knn[n*KNNK+3];
    float v = g_xw2[n*HIDD+c]*nf + g_xw2[k0*HIDD+c]*nf + g_xw2[k1*HIDD+c]*nf
            + g_xw2[k2*HIDD+c]*nf + g_xw2[k3*HIDD+c]*nf;
    v += b2[c];
    g_h2[n*HIDD + c] = fmaxf(v, 0.f);
}

// s = softmax(h2 @ Wp + bp); 8 nodes/block, 512 thr, Wp staged in smem
#define SNODES 8
__global__ void k_s(const float* __restrict__ Wp, const float* __restrict__ bp,
                    float* __restrict__ sout) {
    __shared__ float wps[HIDD*NC];        // 32KB
    __shared__ float hr[SNODES][HIDD];    // 4KB
    __shared__ float red[SNODES][NC];     // 2KB
    int t = threadIdx.x;
    int n0 = blockIdx.x * SNODES;
    for (int i = t; i < HIDD*NC; i += 512) wps[i] = Wp[i];
    for (int i = t; i < SNODES*HIDD; i += 512) hr[i >> 7][i & 127] = g_h2[n0*HIDD + i];
    __syncthreads();
    int r = t >> 6, c = t & 63;
    float a = bp[c];
#pragma unroll 8
    for (int k = 0; k < HIDD; k++) a = fmaf(hr[r][k], wps[k*NC + c], a);
    red[r][c] = a;
    __syncthreads();
    for (int o = 32; o; o >>= 1) { if (c < o) red[r][c] = fmaxf(red[r][c], red[r][c+o]); __syncthreads(); }
    float mx = red[r][0]; __syncthreads();
    float e = expf(a - mx);
    red[r][c] = e;
    __syncthreads();
    for (int o = 32; o; o >>= 1) { if (c < o) red[r][c] += red[r][c+o]; __syncthreads(); }
    sout[(n0 + r)*NC + c] = e / red[r][0];
}

// pooled[b,c,f] += sum over n-chunk of s[b,n,c]*h2[b,n,f]; grid (8,8,4), 128 thr
__global__ void k_pool(const float* __restrict__ s) {
    __shared__ float ssm[128][9];
    int b = blockIdx.x, cg = blockIdx.y, ch = blockIdx.z, f = threadIdx.x;
    int base = b*NN + ch*(NN/4);
    float acc[8];
#pragma unroll
    for (int j = 0; j < 8; j++) acc[j] = 0.f;
    for (int nt = 0; nt < NN/4; nt += 128) {
#pragma unroll
        for (int j = 0; j < 8; j++) ssm[f][j] = s[(base + nt + f)*NC + cg*8 + j];
        __syncthreads();
#pragma unroll 4
        for (int nn = 0; nn < 128; nn++) {
            float xv = g_h2[(base + nt + nn)*HIDD + f];
#pragma unroll
            for (int j = 0; j < 8; j++) acc[j] += ssm[nn][j] * xv;
        }
        __syncthreads();
    }
#pragma unroll
    for (int j = 0; j < 8; j++) atomicAdd(&g_pool[(b*NC + cg*8 + j)*HIDD + f], acc[j]);
}

// ss[b,c,d] += sum over n-chunk of s[b,n,c]*s[b,n,d]; grid (8,8,4), 64 thr
__global__ void k_ssk(const float* __restrict__ s) {
    __shared__ float ssm[128][9];
    int b = blockIdx.x, cg = blockIdx.y, ch = blockIdx.z, d = threadIdx.x;
    int base = b*NN + ch*(NN/4);
    float acc[8];
#pragma unroll
    for (int j = 0; j < 8; j++) acc[j] = 0.f;
    for (int nt = 0; nt < NN/4; nt += 128) {
        for (int r = d; r < 128; r += NC)
#pragma unroll
            for (int j = 0; j < 8; j++) ssm[r][j] = s[(base + nt + r)*NC + cg*8 + j];
        __syncthreads();
#pragma unroll 4
        for (int nn = 0; nn < 128; nn++) {
            float xv = s[(base + nt + nn)*NC + d];
#pragma unroll
            for (int j = 0; j < 8; j++) acc[j] += ssm[nn][j] * xv;
        }
        __syncthreads();
    }
#pragma unroll
    for (int j = 0; j < 8; j++) atomicAdd(&g_ss[b*NC*NC + (cg*8 + j)*NC + d], acc[j]);
}

// ca[b,c] += sum s*deg ; ssum[b,c] += sum s ; grid (8,16), 64 thr
__global__ void k_ca(const float* __restrict__ s) {
    int b = blockIdx.x, ch = blockIdx.y, c = threadIdx.x;
    int base = b*NN + ch*(NN/16);
    float ca = 0.f, su = 0.f;
#pragma unroll 8
    for (int n = 0; n < NN/16; n++) {
        float sv = s[(base + n)*NC + c];
        ca += sv * (float)g_cnt[base + n];
        su += sv;
    }
    atomicAdd(&g_ca[b*NC + c], ca);
    atomicAdd(&g_ssum[b*NC + c], su);
}

// trace(S^T A S) per graph = sum over edges of dot(s[src], s[dst]); warp per edge
__global__ void k_tr(const int* __restrict__ src, const int* __restrict__ dst,
                     const float* __restrict__ s, int E) {
    __shared__ float bins[BG];
    if (threadIdx.x < BG) bins[threadIdx.x] = 0.f;
    __syncthreads();
    int warp = threadIdx.x >> 5, lane = threadIdx.x & 31;
    int gw = blockIdx.x*(blockDim.x >> 5) + warp;
    int nw = gridDim.x*(blockDim.x >> 5);
    for (int e = gw; e < E; e += nw) {
        int a = src[e], d = dst[e];
        float v = s[a*NC + lane]*s[d*NC + lane] + s[a*NC + 32 + lane]*s[d*NC + 32 + lane];
#pragma unroll
        for (int o = 16; o; o >>= 1) v += __shfl_down_sync(0xffffffffu, v, o);
        if (lane == 0) atomicAdd(&bins[a/NN], v);
    }
    __syncthreads();
    if (threadIdx.x < BG) atomicAdd(&g_tr[threadIdx.x], bins[threadIdx.x]);
}

// selu + log_softmax over f; one block per (b,c) row
__global__ void k_out(float* __restrict__ out) {
    __shared__ float red[HIDD];
    int row = blockIdx.x, f = threadIdx.x;
    float v = g_pool[row*HIDD + f];
    const float alpha = 1.6732632423543772f, scale = 1.0507009873554805f;
    v = scale * (v > 0.f ? v : alpha * expm1f(v));
    red[f] = v; __syncthreads();
    for (int o = 64; o; o >>= 1) { if (f < o) red[f] = fmaxf(red[f], red[f+o]); __syncthreads(); }
    float mx = red[0]; __syncthreads();
    float e = expf(v - mx);
    red[f] = e; __syncthreads();
    for (int o = 64; o; o >>= 1) { if (f < o) red[f] += red[f+o]; __syncthreads(); }
    float lse = logf(red[0]);
    out[row*HIDD + f] = v - mx - lse;
}

// scalar loss = mean(spectral) + mean(ortho) + mean(cluster)
__global__ void k_final(float* __restrict__ loss_out) {
    __shared__ float red[256];
    int t = threadIdx.x;
    float spectral = 0.f, ortho = 0.f, cluster = 0.f;
    for (int b = 0; b < BG; b++) {
        float p = 0.f;
        for (int i = t; i < NC*NC; i += 256) { float v = g_ss[b*NC*NC + i]; p += v*v; }
        red[t] = p; __syncthreads();
        for (int o = 128; o; o >>= 1) { if (t < o) red[t] += red[t+o]; __syncthreads(); }
        float fro = sqrtf(red[0]); __syncthreads();
        p = 0.f;
        for (int i = t; i < NC*NC; i += 256) {
            float v = g_ss[b*NC*NC + i] / fro;
            if ((i >> 6) == (i & 63)) v -= 0.125f;
            p += v*v;
        }
        red[t] = p; __syncthreads();
        for (int o = 128; o; o >>= 1) { if (t < o) red[t] += red[t+o]; __syncthreads(); }
        ortho += sqrtf(red[0]); __syncthreads();
        p = 0.f;
        for (int i = t; i < NC; i += 256) { float v = g_ca[b*NC + i]; p += v*v; }
        red[t] = p; __syncthreads();
        for (int o = 128; o; o >>= 1) { if (t < o) red[t] += red[t+o]; __syncthreads(); }
        float ca2 = red[0]; __syncthreads();
        float m = 0.5f * (float)g_ecnt[b];
        spectral += -(g_tr[b] - ca2 / (2.f*m)) / (2.f*m);
        p = 0.f;
        for (int i = t; i < NC; i += 256) { float v = g_ssum[b*NC + i]; p += v*v; }
        red[t] = p; __syncthreads();
        for (int o = 128; o; o >>= 1) { if (t < o) red[t] += red[t+o]; __syncthreads(); }
        cluster += sqrtf(red[0]) / (float)NN * 8.f - 1.f; __syncthreads();
    }
    if (t == 0)
        loss_out[0] = spectral / (float)BG + ortho / (float)BG + cluster / (float)BG;
}

// ---------------- launch ----------------
extern "C" void kernel_launch(void* const* d_in, const int* in_sizes, int n_in,
                              void* d_out, int out_size) {
    const float* x    = (const float*)d_in[0];
    const int*   esrc = (const int*)  d_in[1];
    const int*   edst = (const int*)  d_in[2];
    const float* W1   = (const float*)d_in[4];
    const float* b1   = (const float*)d_in[5];
    const float* W2   = (const float*)d_in[6];
    const float* b2   = (const float*)d_in[7];
    const float* Wp   = (const float*)d_in[8];
    const float* bp   = (const float*)d_in[9];
    float* out = (float*)d_out;
    int E = in_sizes[1];

    float* loss_out = out + BG*NC*HIDD;        // [65536]
    float* sout     = out + BG*NC*HIDD + 1;    // [65537 ..)

    k_zero<<<(BG*NC*HIDD + 255)/256, 256>>>();
    k_hist<<<(E + 255)/256, 256>>>(esrc, edst, E);
    k_scan<<<1, 1024>>>();
    k_fill<<<(E + 255)/256, 256>>>(esrc, edst, E);
    k_xw1y<<<NODES, HIDD>>>(x, W1);
    k_gcn1<<<NODES, HIDD>>>(b1);
    dim3 kg(BG, NN/128);
    k_knn<<<kg, 128>>>();
    k_xw2<<<NODES/32, HIDD>>>(W2);
    k_gcn2<<<NODES, HIDD>>>(b2);
    k_s<<<NODES/SNODES, 512>>>(Wp, bp, sout);
    dim3 pg(BG, 8, 4);
    k_pool<<<pg, HIDD>>>(sout);
    k_ssk<<<pg, NC>>>(sout);
    dim3 cg(BG, 16);
    k_ca<<<cg, NC>>>(sout);
    k_tr<<<2048, 256>>>(esrc, edst, sout, E);
    k_out<<<BG*NC, HIDD>>>(out);
    k_final<<<1, 256>>>(loss_out);
}